// round 10
// baseline (speedup 1.0000x reference)
#include <cuda_runtime.h>
#include <cuda_fp16.h>
#include <cuda_bf16.h>
#include <cstddef>
#include <cstdint>

#define N_NODES 100000
#define N_EDGES 3200000
#define NQUAD   32          // 128 floats = 32 float4 per node row
#define NTILES  782         // ceil(N_NODES / 128)
#define GEMM_GRID 148

// ---------------- scratch (static __device__, allowed) ----------------
__device__ int     g_edeg[N_NODES];
__device__ float   g_dinv[N_NODES];
__device__ int     g_rowptr[N_NODES + 1];
__device__ int     g_cursor[N_NODES];
__device__ int     g_col[N_EDGES];
__device__ __half2 g_h   [(size_t)N_NODES * 64];   // fp16 UNSCALED GEMM output (256 B/row)
__device__ __half2 g_bufh[(size_t)N_NODES * 64];   // fp16 inter-layer activations
__device__ int     g_bsum[128];
__device__ int     g_boff[128];

static __device__ __forceinline__ int clampi(int v, int lo, int hi) {
    return v < lo ? lo : (v > hi ? hi : v);
}

static __device__ __forceinline__ uint32_t h2u(__half2 h) {
    return *reinterpret_cast<uint32_t*>(&h);
}

// fp16 MMA m16n8k16, fp32 accumulate
static __device__ __forceinline__ void mma_f16(float* c, const uint32_t* a,
                                               uint32_t b0, uint32_t b1) {
    asm volatile(
        "mma.sync.aligned.m16n8k16.row.col.f32.f16.f16.f32 "
        "{%0,%1,%2,%3}, {%4,%5,%6,%7}, {%8,%9}, {%0,%1,%2,%3};\n"
        : "+f"(c[0]), "+f"(c[1]), "+f"(c[2]), "+f"(c[3])
        : "r"(a[0]), "r"(a[1]), "r"(a[2]), "r"(a[3]), "r"(b0), "r"(b1));
}

// ---------------- preprocessing: degree / CSR ----------------
__global__ void k_zero_deg() {
    int i = blockIdx.x * blockDim.x + threadIdx.x;
    if (i < N_NODES) g_edeg[i] = 0;
}

__global__ void k_hist(const int* __restrict__ ei) {
    int e = blockIdx.x * blockDim.x + threadIdx.x;
    if (e < N_EDGES) {
        int d = clampi(ei[N_EDGES + e], 0, N_NODES - 1);
        atomicAdd(&g_edeg[d], 1);
    }
}

__global__ void k_scan1() {
    __shared__ int sh[1024];
    int i = blockIdx.x * 1024 + threadIdx.x;
    int v = (i < N_NODES) ? g_edeg[i] : 0;
    sh[threadIdx.x] = v;
    __syncthreads();
#pragma unroll
    for (int off = 1; off < 1024; off <<= 1) {
        int t = (threadIdx.x >= off) ? sh[threadIdx.x - off] : 0;
        __syncthreads();
        sh[threadIdx.x] += t;
        __syncthreads();
    }
    if (i < N_NODES) g_rowptr[i] = sh[threadIdx.x] - v;  // exclusive
    if (threadIdx.x == 1023) g_bsum[blockIdx.x] = sh[1023];
}

__global__ void k_scan2(int nblk) {
    __shared__ int sh[128];
    int v = (threadIdx.x < nblk) ? g_bsum[threadIdx.x] : 0;
    sh[threadIdx.x] = v;
    __syncthreads();
#pragma unroll
    for (int off = 1; off < 128; off <<= 1) {
        int t = (threadIdx.x >= off) ? sh[threadIdx.x - off] : 0;
        __syncthreads();
        sh[threadIdx.x] += t;
        __syncthreads();
    }
    if (threadIdx.x < nblk) g_boff[threadIdx.x] = sh[threadIdx.x] - v;
}

__global__ void k_scan3() {
    int i = blockIdx.x * blockDim.x + threadIdx.x;
    if (i < N_NODES) {
        int rp = g_rowptr[i] + g_boff[i >> 10];
        g_rowptr[i] = rp;
        g_cursor[i] = rp;
        g_dinv[i]   = rsqrtf((float)(g_edeg[i] + 1));   // +1 self loop, always > 0
    }
    if (i == 0) g_rowptr[N_NODES] = N_EDGES;
}

__global__ void k_scatter(const int* __restrict__ ei) {
    int e = blockIdx.x * blockDim.x + threadIdx.x;
    if (e < N_EDGES) {
        int s = clampi(ei[e], 0, N_NODES - 1);
        int d = clampi(ei[N_EDGES + e], 0, N_NODES - 1);
        int p = atomicAdd(&g_cursor[d], 1);
        if (p >= 0 && p < N_EDGES) g_col[p] = s;
    }
}

// ---------------- persistent fp16 GEMM: g_h[r] = fp16( A[r] @ W )  (UNSCALED) --------
// Reads ONLY harness inputs (FIRST) or g_bufh (!FIRST) + W. No CSR data -> safe to
// overlap with the CSR build streams.
#define AS_STRIDE 68
#define AS_ELEMS  (128 * AS_STRIDE)          // per buffer, in half2
#define BS_STRIDE 136
#define SMEM_GEMM ((2 * AS_ELEMS + 64 * BS_STRIDE) * 4)   // 104448 bytes

template <bool FIRST>
__global__ __launch_bounds__(512) void k_gemm_f16(const float* __restrict__ Aext,
                                                  const float* __restrict__ W) {
    extern __shared__ __align__(16) char smem_raw[];
    __half2* sA = reinterpret_cast<__half2*>(smem_raw);              // 2 x [128][68]
    __half2* sB = reinterpret_cast<__half2*>(smem_raw + 2 * AS_ELEMS * 4); // [64][136]

    const int tid  = threadIdx.x;
    const int w    = tid >> 5, lane = tid & 31;
    const int wm   = w & 3;            // row base wm*32
    const int wn   = w >> 2;           // col base wn*32
    const int gid  = lane >> 2, tig = lane & 3;

    const float4* A4 = reinterpret_cast<const float4*>(Aext);
    const uint2*  B2 = reinterpret_cast<const uint2*>(g_bufh);   // 32 uint2 per row
    const float4* W4 = reinterpret_cast<const float4*>(W);

    // ---- load W once: 64 kpairs x 32 quads = 2048 items, 4 per thread ----
#pragma unroll
    for (int j = 0; j < 4; j++) {
        int i = tid + j * 512;
        int r = i >> 5, q = i & 31;
        float4 v0 = W4[(size_t)(2 * r    ) * NQUAD + q];
        float4 v1 = W4[(size_t)(2 * r + 1) * NQUAD + q];
        uint4 pk;
        pk.x = h2u(__floats2half2_rn(v0.x, v1.x));
        pk.y = h2u(__floats2half2_rn(v0.y, v1.y));
        pk.z = h2u(__floats2half2_rn(v0.z, v1.z));
        pk.w = h2u(__floats2half2_rn(v0.w, v1.w));
        *reinterpret_cast<uint4*>(&sB[r * BS_STRIDE + q * 4]) = pk;
    }

    // ---- prefetch first A tile into regs (as half2 words) ----
    int mt = blockIdx.x;
    uint32_t stage[16];
    {
        int m0 = mt * 128;
#pragma unroll
        for (int j = 0; j < 8; j++) {
            int i = tid + j * 512;
            int r = i >> 5, q = i & 31;
            int row = m0 + r;
            if (FIRST) {
                float4 v = make_float4(0.f, 0.f, 0.f, 0.f);
                if (row < N_NODES) v = A4[(size_t)row * NQUAD + q];
                stage[j * 2    ] = h2u(__floats2half2_rn(v.x, v.y));
                stage[j * 2 + 1] = h2u(__floats2half2_rn(v.z, v.w));
            } else {
                uint2 p = make_uint2(0u, 0u);
                if (row < N_NODES) p = B2[(size_t)row * 32 + q];
                stage[j * 2    ] = p.x;
                stage[j * 2 + 1] = p.y;
            }
        }
    }

    int buf = 0;
    while (mt < NTILES) {
        const int m0 = mt * 128;
        // ---- store staged A tile to smem buffer ----
        __half2* A = sA + buf * AS_ELEMS;
#pragma unroll
        for (int j = 0; j < 8; j++) {
            int i = tid + j * 512;
            int r = i >> 5, q = i & 31;
            uint2 p = make_uint2(stage[j * 2], stage[j * 2 + 1]);
            *reinterpret_cast<uint2*>(&A[r * AS_STRIDE + q * 2]) = p;
        }
        __syncthreads();

        // ---- prefetch next tile while computing ----
        const int mnext = mt + GEMM_GRID;
        if (mnext < NTILES) {
            int m0n = mnext * 128;
#pragma unroll
            for (int j = 0; j < 8; j++) {
                int i = tid + j * 512;
                int r = i >> 5, q = i & 31;
                int row = m0n + r;
                if (FIRST) {
                    float4 v = make_float4(0.f, 0.f, 0.f, 0.f);
                    if (row < N_NODES) v = A4[(size_t)row * NQUAD + q];
                    stage[j * 2    ] = h2u(__floats2half2_rn(v.x, v.y));
                    stage[j * 2 + 1] = h2u(__floats2half2_rn(v.z, v.w));
                } else {
                    uint2 p = make_uint2(0u, 0u);
                    if (row < N_NODES) p = B2[(size_t)row * 32 + q];
                    stage[j * 2    ] = p.x;
                    stage[j * 2 + 1] = p.y;
                }
            }
        }

        // ---- compute: 8 k16 chunks ----
        float acc[2][4][4] = {};
#pragma unroll
        for (int c = 0; c < 8; c++) {
            const int h2 = c * 8;                // half2 (A) / kpair (B) base
            uint32_t af[2][4];
#pragma unroll
            for (int fm = 0; fm < 2; fm++) {
                int rb = wm * 32 + fm * 16 + gid;
                const __half2* ar0 = &A[rb * AS_STRIDE];
                const __half2* ar1 = &A[(rb + 8) * AS_STRIDE];
                af[fm][0] = h2u(ar0[h2 + tig]);
                af[fm][1] = h2u(ar1[h2 + tig]);
                af[fm][2] = h2u(ar0[h2 + tig + 4]);
                af[fm][3] = h2u(ar1[h2 + tig + 4]);
            }
#pragma unroll
            for (int fn = 0; fn < 4; fn++) {
                int cn = wn * 32 + fn * 8 + gid;
                uint32_t b0 = h2u(sB[(h2 + tig    ) * BS_STRIDE + cn]);
                uint32_t b1 = h2u(sB[(h2 + tig + 4) * BS_STRIDE + cn]);
                mma_f16(acc[0][fn], af[0], b0, b1);
                mma_f16(acc[1][fn], af[1], b0, b1);
            }
        }

        // ---- epilogue: store UNSCALED fp16 (no g_dinv dependency!) ----
#pragma unroll
        for (int fm = 0; fm < 2; fm++) {
            int r0 = m0 + wm * 32 + fm * 16 + gid;
            int r1 = r0 + 8;
#pragma unroll
            for (int fn = 0; fn < 4; fn++) {
                int h2i = wn * 16 + fn * 4 + tig;
                if (r0 < N_NODES)
                    g_h[(size_t)r0 * 64 + h2i] =
                        __floats2half2_rn(acc[fm][fn][0], acc[fm][fn][1]);
                if (r1 < N_NODES)
                    g_h[(size_t)r1 * 64 + h2i] =
                        __floats2half2_rn(acc[fm][fn][2], acc[fm][fn][3]);
            }
        }

        mt = mnext;
        buf ^= 1;
    }
}

// ---------------- aggregation: warp per node, norm applied here ----------
// out[d] = relu( dv_d * ( dv_d*h[d] + sum_s dv_s*h[s] ) + b )
template <bool LAST>
__global__ __launch_bounds__(256) void k_agg(const float* __restrict__ bias,
                                             float* __restrict__ outExt) {
    int gw   = (blockIdx.x * blockDim.x + threadIdx.x) >> 5;
    int lane = threadIdx.x & 31;
    if (gw >= N_NODES) return;

    const uint2* H = reinterpret_cast<const uint2*>(g_h);   // 32 uint2 per row
    const float dv = g_dinv[gw];

    float4 acc;
    {
        uint2 u = H[(size_t)gw * 32 + lane];                // self-loop term * dv
        float2 f0 = __half22float2(*reinterpret_cast<__half2*>(&u.x));
        float2 f1 = __half22float2(*reinterpret_cast<__half2*>(&u.y));
        acc = make_float4(f0.x * dv, f0.y * dv, f1.x * dv, f1.y * dv);
    }
    const int beg = g_rowptr[gw], end = g_rowptr[gw + 1];

    for (int j = beg; j < end; j += 32) {
        int jl  = j + lane;
        int idx = (jl < end) ? g_col[jl] : 0;
        float ds = g_dinv[idx];                  // per-source norm (idx always valid)
        int cnt = min(32, end - j);
        int t = 0;
        for (; t + 8 <= cnt; t += 8) {           // 8 independent gathers in flight
            uint2 v[8]; float wv[8];
#pragma unroll
            for (int u = 0; u < 8; u++) {
                int s  = __shfl_sync(0xffffffffu, idx, t + u);
                wv[u]  = __shfl_sync(0xffffffffu, ds,  t + u);
                v[u]   = H[(size_t)s * 32 + lane];
            }
#pragma unroll
            for (int u = 0; u < 8; u++) {
                float2 f0 = __half22float2(*reinterpret_cast<__half2*>(&v[u].x));
                float2 f1 = __half22float2(*reinterpret_cast<__half2*>(&v[u].y));
                acc.x = fmaf(f0.x, wv[u], acc.x);
                acc.y = fmaf(f0.y, wv[u], acc.y);
                acc.z = fmaf(f1.x, wv[u], acc.z);
                acc.w = fmaf(f1.y, wv[u], acc.w);
            }
        }
        for (; t < cnt; t++) {
            int s  = __shfl_sync(0xffffffffu, idx, t);
            float ws = __shfl_sync(0xffffffffu, ds, t);
            uint2 u = H[(size_t)s * 32 + lane];
            float2 f0 = __half22float2(*reinterpret_cast<__half2*>(&u.x));
            float2 f1 = __half22float2(*reinterpret_cast<__half2*>(&u.y));
            acc.x = fmaf(f0.x, ws, acc.x);
            acc.y = fmaf(f0.y, ws, acc.y);
            acc.z = fmaf(f1.x, ws, acc.z);
            acc.w = fmaf(f1.y, ws, acc.w);
        }
    }

    float4 bb = reinterpret_cast<const float4*>(bias)[lane];
    float4 o;
    o.x = fmaxf(fmaf(acc.x, dv, bb.x), 0.f);
    o.y = fmaxf(fmaf(acc.y, dv, bb.y), 0.f);
    o.z = fmaxf(fmaf(acc.z, dv, bb.z), 0.f);
    o.w = fmaxf(fmaf(acc.w, dv, bb.w), 0.f);
    if (LAST) {
        reinterpret_cast<float4*>(outExt)[(size_t)gw * NQUAD + lane] = o;
    } else {
        uint2 p;
        p.x = h2u(__floats2half2_rn(o.x, o.y));
        p.y = h2u(__floats2half2_rn(o.z, o.w));
        reinterpret_cast<uint2*>(g_bufh)[(size_t)gw * 32 + lane] = p;
    }
}

// ---------------- launch ----------------
extern "C" void kernel_launch(void* const* d_in, const int* in_sizes, int n_in,
                              void* d_out, int out_size) {
    const float* x  = (const float*)d_in[0];
    const int*   ei = (const int*)d_in[1];          // int32 edge_index
    const float* W0 = (const float*)d_in[2];
    const float* b0 = (const float*)d_in[3];
    const float* W1 = (const float*)d_in[4];
    const float* b1 = (const float*)d_in[5];
    const float* W2 = (const float*)d_in[6];
    const float* b2 = (const float*)d_in[7];
    float* out = (float*)d_out;

    const int nodeBlocks = (N_NODES + 255) / 256;
    const int edgeBlocks = (N_EDGES + 255) / 256;
    const int scanBlocks = (N_NODES + 1023) / 1024;   // 98
    const int aggBlocks  = (N_NODES * 32 + 255) / 256;

    cudaFuncSetAttribute(k_gemm_f16<true>,
                         cudaFuncAttributeMaxDynamicSharedMemorySize, SMEM_GEMM);
    cudaFuncSetAttribute(k_gemm_f16<false>,
                         cudaFuncAttributeMaxDynamicSharedMemorySize, SMEM_GEMM);

    // Fork-join: CSR build on side stream s2; gemm0 (now touching NO CSR data)
    // overlaps on the main stream. Stream/event objects persist (no device mem).
    cudaStream_t s2;
    cudaStreamCreate(&s2);
    cudaEvent_t eF, eJ;
    cudaEventCreateWithFlags(&eF, cudaEventDisableTiming);
    cudaEventCreateWithFlags(&eJ, cudaEventDisableTiming);

    cudaEventRecord(eF, 0);
    cudaStreamWaitEvent(s2, eF, 0);

    k_zero_deg<<<nodeBlocks, 256, 0, s2>>>();
    k_hist    <<<edgeBlocks, 256, 0, s2>>>(ei);
    k_scan1   <<<scanBlocks, 1024, 0, s2>>>();
    // gemm0 on main stream, concurrent with CSR build (disjoint data)
    k_gemm_f16<true><<<GEMM_GRID, 512, SMEM_GEMM>>>(x, W0);
    k_scan2   <<<1, 128, 0, s2>>>(scanBlocks);
    k_scan3   <<<nodeBlocks, 256, 0, s2>>>();
    k_scatter <<<edgeBlocks, 256, 0, s2>>>(ei);

    cudaEventRecord(eJ, s2);
    cudaStreamWaitEvent(0, eJ, 0);

    // layer 0 aggregation, then layers 1-2 sequential on main stream
    k_agg     <false><<<aggBlocks, 256>>>(b0, nullptr);
    k_gemm_f16<false><<<GEMM_GRID, 512, SMEM_GEMM>>>(nullptr, W1);
    k_agg     <false><<<aggBlocks, 256>>>(b1, nullptr);
    k_gemm_f16<false><<<GEMM_GRID, 512, SMEM_GEMM>>>(nullptr, W2);
    k_agg     <true ><<<aggBlocks, 256>>>(b2, out);
}

// round 11
// speedup vs baseline: 1.1045x; 1.1045x over previous
#include <cuda_runtime.h>
#include <cuda_fp16.h>
#include <cuda_bf16.h>
#include <cstddef>
#include <cstdint>

#define N_NODES 100000
#define N_EDGES 3200000
#define NQUAD   32          // 128 floats = 32 float4 per node row
#define NTILES  782         // ceil(N_NODES / 128)
#define GEMM_GRID 148

// ---------------- scratch (static __device__, allowed) ----------------
__device__ int     g_edeg[N_NODES];
__device__ float   g_dinv[N_NODES];
__device__ int     g_rowptr[N_NODES + 1];
__device__ int     g_cursor[N_NODES];
__device__ int     g_col[N_EDGES];
__device__ __half2 g_h   [(size_t)N_NODES * 64];   // fp16 scaled GEMM output (256 B/row)
__device__ __half2 g_bufh[(size_t)N_NODES * 64];   // fp16 inter-layer activations
__device__ int     g_bsum[128];
__device__ int     g_boff[128];

static __device__ __forceinline__ int clampi(int v, int lo, int hi) {
    return v < lo ? lo : (v > hi ? hi : v);
}

static __device__ __forceinline__ uint32_t h2u(__half2 h) {
    return *reinterpret_cast<uint32_t*>(&h);
}

// fp16 MMA m16n8k16, fp32 accumulate
static __device__ __forceinline__ void mma_f16(float* c, const uint32_t* a,
                                               uint32_t b0, uint32_t b1) {
    asm volatile(
        "mma.sync.aligned.m16n8k16.row.col.f32.f16.f16.f32 "
        "{%0,%1,%2,%3}, {%4,%5,%6,%7}, {%8,%9}, {%0,%1,%2,%3};\n"
        : "+f"(c[0]), "+f"(c[1]), "+f"(c[2]), "+f"(c[3])
        : "r"(a[0]), "r"(a[1]), "r"(a[2]), "r"(a[3]), "r"(b0), "r"(b1));
}

// ---------------- preprocessing: degree / CSR ----------------
__global__ void k_zero_deg() {
    int i = blockIdx.x * blockDim.x + threadIdx.x;
    if (i < N_NODES) g_edeg[i] = 0;
}

__global__ void k_hist(const int* __restrict__ ei) {
    int e = blockIdx.x * blockDim.x + threadIdx.x;
    if (e < N_EDGES) {
        int d = clampi(ei[N_EDGES + e], 0, N_NODES - 1);
        atomicAdd(&g_edeg[d], 1);
    }
}

__global__ void k_scan1() {
    __shared__ int sh[1024];
    int i = blockIdx.x * 1024 + threadIdx.x;
    int v = (i < N_NODES) ? g_edeg[i] : 0;
    sh[threadIdx.x] = v;
    __syncthreads();
#pragma unroll
    for (int off = 1; off < 1024; off <<= 1) {
        int t = (threadIdx.x >= off) ? sh[threadIdx.x - off] : 0;
        __syncthreads();
        sh[threadIdx.x] += t;
        __syncthreads();
    }
    if (i < N_NODES) g_rowptr[i] = sh[threadIdx.x] - v;  // exclusive
    if (threadIdx.x == 1023) g_bsum[blockIdx.x] = sh[1023];
}

__global__ void k_scan2(int nblk) {
    __shared__ int sh[128];
    int v = (threadIdx.x < nblk) ? g_bsum[threadIdx.x] : 0;
    sh[threadIdx.x] = v;
    __syncthreads();
#pragma unroll
    for (int off = 1; off < 128; off <<= 1) {
        int t = (threadIdx.x >= off) ? sh[threadIdx.x - off] : 0;
        __syncthreads();
        sh[threadIdx.x] += t;
        __syncthreads();
    }
    if (threadIdx.x < nblk) g_boff[threadIdx.x] = sh[threadIdx.x] - v;
}

__global__ void k_scan3() {
    int i = blockIdx.x * blockDim.x + threadIdx.x;
    if (i < N_NODES) {
        int rp = g_rowptr[i] + g_boff[i >> 10];
        g_rowptr[i] = rp;
        g_cursor[i] = rp;
        g_dinv[i]   = rsqrtf((float)(g_edeg[i] + 1));   // +1 self loop, always > 0
    }
    if (i == 0) g_rowptr[N_NODES] = N_EDGES;
}

__global__ void k_scatter(const int* __restrict__ ei) {
    int e = blockIdx.x * blockDim.x + threadIdx.x;
    if (e < N_EDGES) {
        int s = clampi(ei[e], 0, N_NODES - 1);
        int d = clampi(ei[N_EDGES + e], 0, N_NODES - 1);
        int p = atomicAdd(&g_cursor[d], 1);
        if (p >= 0 && p < N_EDGES) g_col[p] = s;
    }
}

// ---------------- post-join scale for layer 0: g_h[r] *= dinv[r] ----------------
__global__ __launch_bounds__(256) void k_scale() {
    int i = blockIdx.x * blockDim.x + threadIdx.x;   // uint2 index (8 B granules)
    if (i < N_NODES * 32) {
        float dv = g_dinv[i >> 5];
        uint2 u = reinterpret_cast<uint2*>(g_h)[i];
        float2 f0 = __half22float2(*reinterpret_cast<__half2*>(&u.x));
        float2 f1 = __half22float2(*reinterpret_cast<__half2*>(&u.y));
        uint2 p;
        p.x = h2u(__floats2half2_rn(f0.x * dv, f0.y * dv));
        p.y = h2u(__floats2half2_rn(f1.x * dv, f1.y * dv));
        reinterpret_cast<uint2*>(g_h)[i] = p;
    }
}

// ---------------- persistent fp16 GEMM ----------------
// FIRST: A = external fp32 x; epilogue stores UNSCALED (no CSR dependency -> can
//        overlap the CSR build; k_scale applies dinv afterwards).
// !FIRST: A = g_bufh fp16; epilogue scales by dinv (CSR ready by then).
#define AS_STRIDE 68
#define AS_ELEMS  (128 * AS_STRIDE)          // per buffer, in half2
#define BS_STRIDE 136
#define SMEM_GEMM ((2 * AS_ELEMS + 64 * BS_STRIDE) * 4)   // 104448 bytes

template <bool FIRST>
__global__ __launch_bounds__(512) void k_gemm_f16(const float* __restrict__ Aext,
                                                  const float* __restrict__ W) {
    extern __shared__ __align__(16) char smem_raw[];
    __half2* sA = reinterpret_cast<__half2*>(smem_raw);              // 2 x [128][68]
    __half2* sB = reinterpret_cast<__half2*>(smem_raw + 2 * AS_ELEMS * 4); // [64][136]

    const int tid  = threadIdx.x;
    const int w    = tid >> 5, lane = tid & 31;
    const int wm   = w & 3;            // row base wm*32
    const int wn   = w >> 2;           // col base wn*32
    const int gid  = lane >> 2, tig = lane & 3;

    const float4* A4 = reinterpret_cast<const float4*>(Aext);
    const uint2*  B2 = reinterpret_cast<const uint2*>(g_bufh);   // 32 uint2 per row
    const float4* W4 = reinterpret_cast<const float4*>(W);

    // ---- load W once: 64 kpairs x 32 quads = 2048 items, 4 per thread ----
#pragma unroll
    for (int j = 0; j < 4; j++) {
        int i = tid + j * 512;
        int r = i >> 5, q = i & 31;
        float4 v0 = W4[(size_t)(2 * r    ) * NQUAD + q];
        float4 v1 = W4[(size_t)(2 * r + 1) * NQUAD + q];
        uint4 pk;
        pk.x = h2u(__floats2half2_rn(v0.x, v1.x));
        pk.y = h2u(__floats2half2_rn(v0.y, v1.y));
        pk.z = h2u(__floats2half2_rn(v0.z, v1.z));
        pk.w = h2u(__floats2half2_rn(v0.w, v1.w));
        *reinterpret_cast<uint4*>(&sB[r * BS_STRIDE + q * 4]) = pk;
    }

    // ---- prefetch first A tile into regs (as half2 words) ----
    int mt = blockIdx.x;
    uint32_t stage[16];
    {
        int m0 = mt * 128;
#pragma unroll
        for (int j = 0; j < 8; j++) {
            int i = tid + j * 512;
            int r = i >> 5, q = i & 31;
            int row = m0 + r;
            if (FIRST) {
                float4 v = make_float4(0.f, 0.f, 0.f, 0.f);
                if (row < N_NODES) v = A4[(size_t)row * NQUAD + q];
                stage[j * 2    ] = h2u(__floats2half2_rn(v.x, v.y));
                stage[j * 2 + 1] = h2u(__floats2half2_rn(v.z, v.w));
            } else {
                uint2 p = make_uint2(0u, 0u);
                if (row < N_NODES) p = B2[(size_t)row * 32 + q];
                stage[j * 2    ] = p.x;
                stage[j * 2 + 1] = p.y;
            }
        }
    }

    int buf = 0;
    while (mt < NTILES) {
        const int m0 = mt * 128;
        // ---- store staged A tile to smem buffer ----
        __half2* A = sA + buf * AS_ELEMS;
#pragma unroll
        for (int j = 0; j < 8; j++) {
            int i = tid + j * 512;
            int r = i >> 5, q = i & 31;
            uint2 p = make_uint2(stage[j * 2], stage[j * 2 + 1]);
            *reinterpret_cast<uint2*>(&A[r * AS_STRIDE + q * 2]) = p;
        }
        __syncthreads();

        // ---- prefetch next tile while computing ----
        const int mnext = mt + GEMM_GRID;
        if (mnext < NTILES) {
            int m0n = mnext * 128;
#pragma unroll
            for (int j = 0; j < 8; j++) {
                int i = tid + j * 512;
                int r = i >> 5, q = i & 31;
                int row = m0n + r;
                if (FIRST) {
                    float4 v = make_float4(0.f, 0.f, 0.f, 0.f);
                    if (row < N_NODES) v = A4[(size_t)row * NQUAD + q];
                    stage[j * 2    ] = h2u(__floats2half2_rn(v.x, v.y));
                    stage[j * 2 + 1] = h2u(__floats2half2_rn(v.z, v.w));
                } else {
                    uint2 p = make_uint2(0u, 0u);
                    if (row < N_NODES) p = B2[(size_t)row * 32 + q];
                    stage[j * 2    ] = p.x;
                    stage[j * 2 + 1] = p.y;
                }
            }
        }

        // ---- compute: 8 k16 chunks ----
        float acc[2][4][4] = {};
#pragma unroll
        for (int c = 0; c < 8; c++) {
            const int h2 = c * 8;                // half2 (A) / kpair (B) base
            uint32_t af[2][4];
#pragma unroll
            for (int fm = 0; fm < 2; fm++) {
                int rb = wm * 32 + fm * 16 + gid;
                const __half2* ar0 = &A[rb * AS_STRIDE];
                const __half2* ar1 = &A[(rb + 8) * AS_STRIDE];
                af[fm][0] = h2u(ar0[h2 + tig]);
                af[fm][1] = h2u(ar1[h2 + tig]);
                af[fm][2] = h2u(ar0[h2 + tig + 4]);
                af[fm][3] = h2u(ar1[h2 + tig + 4]);
            }
#pragma unroll
            for (int fn = 0; fn < 4; fn++) {
                int cn = wn * 32 + fn * 8 + gid;
                uint32_t b0 = h2u(sB[(h2 + tig    ) * BS_STRIDE + cn]);
                uint32_t b1 = h2u(sB[(h2 + tig + 4) * BS_STRIDE + cn]);
                mma_f16(acc[0][fn], af[0], b0, b1);
                mma_f16(acc[1][fn], af[1], b0, b1);
            }
        }

        // ---- epilogue ----
#pragma unroll
        for (int fm = 0; fm < 2; fm++) {
            int r0 = m0 + wm * 32 + fm * 16 + gid;
            int r1 = r0 + 8;
            float d0 = 1.f, d1 = 1.f;
            if (!FIRST) {
                d0 = (r0 < N_NODES) ? g_dinv[r0] : 0.f;
                d1 = (r1 < N_NODES) ? g_dinv[r1] : 0.f;
            }
#pragma unroll
            for (int fn = 0; fn < 4; fn++) {
                int h2i = wn * 16 + fn * 4 + tig;
                if (r0 < N_NODES)
                    g_h[(size_t)r0 * 64 + h2i] =
                        __floats2half2_rn(acc[fm][fn][0] * d0, acc[fm][fn][1] * d0);
                if (r1 < N_NODES)
                    g_h[(size_t)r1 * 64 + h2i] =
                        __floats2half2_rn(acc[fm][fn][2] * d1, acc[fm][fn][3] * d1);
            }
        }

        mt = mnext;
        buf ^= 1;
    }
}

// ---------------- aggregation: warp per node, pre-scaled rows (R8 form) ----------
// out[d] = relu( dv_d * ( g[d] + sum_s g[s] ) + b ),  g already carries dinv[s]
template <bool LAST>
__global__ __launch_bounds__(256) void k_agg(const float* __restrict__ bias,
                                             float* __restrict__ outExt) {
    int gw   = (blockIdx.x * blockDim.x + threadIdx.x) >> 5;
    int lane = threadIdx.x & 31;
    if (gw >= N_NODES) return;

    const uint2* H = reinterpret_cast<const uint2*>(g_h);   // 32 uint2 per row

    float4 acc;
    {
        uint2 u = H[(size_t)gw * 32 + lane];                // self-loop term
        float2 f0 = __half22float2(*reinterpret_cast<__half2*>(&u.x));
        float2 f1 = __half22float2(*reinterpret_cast<__half2*>(&u.y));
        acc = make_float4(f0.x, f0.y, f1.x, f1.y);
    }
    const int beg = g_rowptr[gw], end = g_rowptr[gw + 1];

    for (int j = beg; j < end; j += 32) {
        int jl  = j + lane;
        int idx = (jl < end) ? g_col[jl] : 0;
        int cnt = min(32, end - j);
        int t = 0;
        for (; t + 8 <= cnt; t += 8) {           // 8 independent gathers in flight
            uint2 v[8];
#pragma unroll
            for (int u = 0; u < 8; u++) {
                int s = __shfl_sync(0xffffffffu, idx, t + u);
                v[u] = H[(size_t)s * 32 + lane];
            }
#pragma unroll
            for (int u = 0; u < 8; u++) {
                float2 f0 = __half22float2(*reinterpret_cast<__half2*>(&v[u].x));
                float2 f1 = __half22float2(*reinterpret_cast<__half2*>(&v[u].y));
                acc.x += f0.x; acc.y += f0.y; acc.z += f1.x; acc.w += f1.y;
            }
        }
        for (; t < cnt; t++) {
            int s = __shfl_sync(0xffffffffu, idx, t);
            uint2 u = H[(size_t)s * 32 + lane];
            float2 f0 = __half22float2(*reinterpret_cast<__half2*>(&u.x));
            float2 f1 = __half22float2(*reinterpret_cast<__half2*>(&u.y));
            acc.x += f0.x; acc.y += f0.y; acc.z += f1.x; acc.w += f1.y;
        }
    }

    float dv  = g_dinv[gw];
    float4 bb = reinterpret_cast<const float4*>(bias)[lane];
    float4 o;
    o.x = fmaxf(fmaf(acc.x, dv, bb.x), 0.f);
    o.y = fmaxf(fmaf(acc.y, dv, bb.y), 0.f);
    o.z = fmaxf(fmaf(acc.z, dv, bb.z), 0.f);
    o.w = fmaxf(fmaf(acc.w, dv, bb.w), 0.f);
    if (LAST) {
        reinterpret_cast<float4*>(outExt)[(size_t)gw * NQUAD + lane] = o;
    } else {
        uint2 p;
        p.x = h2u(__floats2half2_rn(o.x, o.y));
        p.y = h2u(__floats2half2_rn(o.z, o.w));
        reinterpret_cast<uint2*>(g_bufh)[(size_t)gw * 32 + lane] = p;
    }
}

// ---------------- launch ----------------
extern "C" void kernel_launch(void* const* d_in, const int* in_sizes, int n_in,
                              void* d_out, int out_size) {
    const float* x  = (const float*)d_in[0];
    const int*   ei = (const int*)d_in[1];          // int32 edge_index
    const float* W0 = (const float*)d_in[2];
    const float* b0 = (const float*)d_in[3];
    const float* W1 = (const float*)d_in[4];
    const float* b1 = (const float*)d_in[5];
    const float* W2 = (const float*)d_in[6];
    const float* b2 = (const float*)d_in[7];
    float* out = (float*)d_out;

    const int nodeBlocks  = (N_NODES + 255) / 256;
    const int edgeBlocks  = (N_EDGES + 255) / 256;
    const int scanBlocks  = (N_NODES + 1023) / 1024;   // 98
    const int aggBlocks   = (N_NODES * 32 + 255) / 256;
    const int scaleBlocks = (N_NODES * 32 + 255) / 256;

    cudaFuncSetAttribute(k_gemm_f16<true>,
                         cudaFuncAttributeMaxDynamicSharedMemorySize, SMEM_GEMM);
    cudaFuncSetAttribute(k_gemm_f16<false>,
                         cudaFuncAttributeMaxDynamicSharedMemorySize, SMEM_GEMM);

    // Fork-join: CSR build on side stream s2; gemm0 (unscaled, touches NO CSR
    // data) overlaps on the main stream. Stream/event objects persist.
    cudaStream_t s2;
    cudaStreamCreate(&s2);
    cudaEvent_t eF, eJ;
    cudaEventCreateWithFlags(&eF, cudaEventDisableTiming);
    cudaEventCreateWithFlags(&eJ, cudaEventDisableTiming);

    cudaEventRecord(eF, 0);
    cudaStreamWaitEvent(s2, eF, 0);

    k_zero_deg<<<nodeBlocks, 256, 0, s2>>>();
    k_hist    <<<edgeBlocks, 256, 0, s2>>>(ei);
    k_scan1   <<<scanBlocks, 1024, 0, s2>>>();
    // gemm0 on main stream, concurrent with CSR build (disjoint data)
    k_gemm_f16<true><<<GEMM_GRID, 512, SMEM_GEMM>>>(x, W0);
    k_scan2   <<<1, 128, 0, s2>>>(scanBlocks);
    k_scan3   <<<nodeBlocks, 256, 0, s2>>>();
    k_scatter <<<edgeBlocks, 256, 0, s2>>>(ei);

    cudaEventRecord(eJ, s2);
    cudaStreamWaitEvent(0, eJ, 0);

    // apply layer-0 dinv scaling, then the sequential chain
    k_scale   <<<scaleBlocks, 256>>>();
    k_agg     <false><<<aggBlocks, 256>>>(b0, nullptr);
    k_gemm_f16<false><<<GEMM_GRID, 512, SMEM_GEMM>>>(nullptr, W1);
    k_agg     <false><<<aggBlocks, 256>>>(b1, nullptr);
    k_gemm_f16<false><<<GEMM_GRID, 512, SMEM_GEMM>>>(nullptr, W2);
    k_agg     <true ><<<aggBlocks, 256>>>(b2, out);
}

// round 12
// speedup vs baseline: 1.1472x; 1.0387x over previous
#include <cuda_runtime.h>
#include <cuda_fp16.h>
#include <cuda_bf16.h>
#include <cstddef>
#include <cstdint>

#define N_NODES 100000
#define N_EDGES 3200000
#define NQUAD   32          // 128 floats = 32 float4 per node row
#define NTILES  782         // ceil(N_NODES / 128)
#define GEMM_GRID 148

// ---------------- scratch (static __device__, allowed) ----------------
__device__ int     g_edeg[N_NODES];
__device__ float   g_dinv[N_NODES];
__device__ int     g_rowptr[N_NODES + 1];
__device__ int     g_cursor[N_NODES];
__device__ int     g_col[N_EDGES];
__device__ __half2 g_h   [(size_t)N_NODES * 64];   // fp16 scaled GEMM output (256 B/row)
__device__ __half2 g_bufh[(size_t)N_NODES * 64];   // fp16 inter-layer activations
__device__ int     g_bsum[128];

static __device__ __forceinline__ int clampi(int v, int lo, int hi) {
    return v < lo ? lo : (v > hi ? hi : v);
}

static __device__ __forceinline__ uint32_t h2u(__half2 h) {
    return *reinterpret_cast<uint32_t*>(&h);
}

// fp16 MMA m16n8k16, fp32 accumulate
static __device__ __forceinline__ void mma_f16(float* c, const uint32_t* a,
                                               uint32_t b0, uint32_t b1) {
    asm volatile(
        "mma.sync.aligned.m16n8k16.row.col.f32.f16.f16.f32 "
        "{%0,%1,%2,%3}, {%4,%5,%6,%7}, {%8,%9}, {%0,%1,%2,%3};\n"
        : "+f"(c[0]), "+f"(c[1]), "+f"(c[2]), "+f"(c[3])
        : "r"(a[0]), "r"(a[1]), "r"(a[2]), "r"(a[3]), "r"(b0), "r"(b1));
}

static __device__ __forceinline__ void ldsm_x4(uint32_t& r0, uint32_t& r1,
                                               uint32_t& r2, uint32_t& r3,
                                               uint32_t saddr) {
    asm volatile("ldmatrix.sync.aligned.m8n8.x4.shared.b16 {%0,%1,%2,%3}, [%4];"
                 : "=r"(r0), "=r"(r1), "=r"(r2), "=r"(r3) : "r"(saddr));
}

// ---------------- preprocessing: degree / CSR ----------------
__global__ void k_zero_deg() {
    int i = blockIdx.x * blockDim.x + threadIdx.x;
    if (i < N_NODES) g_edeg[i] = 0;
}

__global__ void k_hist(const int* __restrict__ ei) {
    int e = blockIdx.x * blockDim.x + threadIdx.x;
    if (e < N_EDGES) {
        int d = clampi(ei[N_EDGES + e], 0, N_NODES - 1);
        atomicAdd(&g_edeg[d], 1);
    }
}

__global__ void k_scan1() {
    __shared__ int sh[1024];
    int i = blockIdx.x * 1024 + threadIdx.x;
    int v = (i < N_NODES) ? g_edeg[i] : 0;
    sh[threadIdx.x] = v;
    __syncthreads();
#pragma unroll
    for (int off = 1; off < 1024; off <<= 1) {
        int t = (threadIdx.x >= off) ? sh[threadIdx.x - off] : 0;
        __syncthreads();
        sh[threadIdx.x] += t;
        __syncthreads();
    }
    if (i < N_NODES) g_rowptr[i] = sh[threadIdx.x] - v;  // exclusive
    if (threadIdx.x == 1023) g_bsum[blockIdx.x] = sh[1023];
}

// scan2 folded in: each 256-node block lies inside ONE scan1 block (1024 | align),
// so one offset = sum of g_bsum[0 .. myblk-1], computed by a 128-wide reduction.
__global__ void k_scan3(int nblk) {
    __shared__ int sh[128];
    const int t = threadIdx.x;
    const int myblk = blockIdx.x >> 2;     // scan1 block containing our 256 nodes
    if (t < 128) sh[t] = (t < nblk && t < myblk) ? g_bsum[t] : 0;
    __syncthreads();
#pragma unroll
    for (int off = 64; off > 0; off >>= 1) {
        if (t < off) sh[t] += sh[t + off];
        __syncthreads();
    }
    const int boff = sh[0];

    int i = blockIdx.x * 256 + t;
    if (i < N_NODES) {
        int rp = g_rowptr[i] + boff;
        g_rowptr[i] = rp;
        g_cursor[i] = rp;
        g_dinv[i]   = rsqrtf((float)(g_edeg[i] + 1));   // +1 self loop, always > 0
    }
    if (i == 0) g_rowptr[N_NODES] = N_EDGES;
}

__global__ void k_scatter(const int* __restrict__ ei) {
    int e = blockIdx.x * blockDim.x + threadIdx.x;
    if (e < N_EDGES) {
        int s = clampi(ei[e], 0, N_NODES - 1);
        int d = clampi(ei[N_EDGES + e], 0, N_NODES - 1);
        int p = atomicAdd(&g_cursor[d], 1);
        if (p >= 0 && p < N_EDGES) g_col[p] = s;
    }
}

// ---------------- post-join scale for layer 0: g_h[r] *= dinv[r] ----------------
// Depends only on scan3 (dinv) + gemm0 (g_h) -> overlaps k_scatter.
__global__ __launch_bounds__(256) void k_scale() {
    int i = blockIdx.x * blockDim.x + threadIdx.x;   // uint2 index (8 B granules)
    if (i < N_NODES * 32) {
        float dv = g_dinv[i >> 5];
        uint2 u = reinterpret_cast<uint2*>(g_h)[i];
        float2 f0 = __half22float2(*reinterpret_cast<__half2*>(&u.x));
        float2 f1 = __half22float2(*reinterpret_cast<__half2*>(&u.y));
        uint2 p;
        p.x = h2u(__floats2half2_rn(f0.x * dv, f0.y * dv));
        p.y = h2u(__floats2half2_rn(f1.x * dv, f1.y * dv));
        reinterpret_cast<uint2*>(g_h)[i] = p;
    }
}

// ---------------- persistent fp16 GEMM ----------------
// FIRST: A = external fp32 x; stores UNSCALED (no CSR dependency -> overlaps CSR).
// !FIRST: A = g_bufh fp16; epilogue scales by dinv.
// A-fragments via ldmatrix.x4 (1 op per fm per chunk instead of 8 LDS.32).
#define AS_STRIDE 68
#define AS_ELEMS  (128 * AS_STRIDE)          // per buffer, in half2
#define BS_STRIDE 136
#define SMEM_GEMM ((2 * AS_ELEMS + 64 * BS_STRIDE) * 4)   // 104448 bytes

template <bool FIRST>
__global__ __launch_bounds__(512) void k_gemm_f16(const float* __restrict__ Aext,
                                                  const float* __restrict__ W) {
    extern __shared__ __align__(16) char smem_raw[];
    __half2* sA = reinterpret_cast<__half2*>(smem_raw);              // 2 x [128][68]
    __half2* sB = reinterpret_cast<__half2*>(smem_raw + 2 * AS_ELEMS * 4); // [64][136]

    const int tid  = threadIdx.x;
    const int w    = tid >> 5, lane = tid & 31;
    const int wm   = w & 3;            // row base wm*32
    const int wn   = w >> 2;           // col base wn*32
    const int gid  = lane >> 2, tig = lane & 3;

    const float4* A4 = reinterpret_cast<const float4*>(Aext);
    const uint2*  B2 = reinterpret_cast<const uint2*>(g_bufh);   // 32 uint2 per row
    const float4* W4 = reinterpret_cast<const float4*>(W);

    // ---- load W once: 64 kpairs x 32 quads = 2048 items, 4 per thread ----
#pragma unroll
    for (int j = 0; j < 4; j++) {
        int i = tid + j * 512;
        int r = i >> 5, q = i & 31;
        float4 v0 = W4[(size_t)(2 * r    ) * NQUAD + q];
        float4 v1 = W4[(size_t)(2 * r + 1) * NQUAD + q];
        uint4 pk;
        pk.x = h2u(__floats2half2_rn(v0.x, v1.x));
        pk.y = h2u(__floats2half2_rn(v0.y, v1.y));
        pk.z = h2u(__floats2half2_rn(v0.z, v1.z));
        pk.w = h2u(__floats2half2_rn(v0.w, v1.w));
        *reinterpret_cast<uint4*>(&sB[r * BS_STRIDE + q * 4]) = pk;
    }

    // ldmatrix lane geometry (per fm): lanes 0-15 -> rows rb0+(lane&15), col 0;
    // lanes 16-31 -> same rows, col +4 half2.
    const int lrow = (lane & 15);
    const int lcol = (lane >> 4) * 4;

    // ---- prefetch first A tile into regs (as half2 words) ----
    int mt = blockIdx.x;
    uint32_t stage[16];
    {
        int m0 = mt * 128;
#pragma unroll
        for (int j = 0; j < 8; j++) {
            int i = tid + j * 512;
            int r = i >> 5, q = i & 31;
            int row = m0 + r;
            if (FIRST) {
                float4 v = make_float4(0.f, 0.f, 0.f, 0.f);
                if (row < N_NODES) v = A4[(size_t)row * NQUAD + q];
                stage[j * 2    ] = h2u(__floats2half2_rn(v.x, v.y));
                stage[j * 2 + 1] = h2u(__floats2half2_rn(v.z, v.w));
            } else {
                uint2 p = make_uint2(0u, 0u);
                if (row < N_NODES) p = B2[(size_t)row * 32 + q];
                stage[j * 2    ] = p.x;
                stage[j * 2 + 1] = p.y;
            }
        }
    }

    int buf = 0;
    while (mt < NTILES) {
        const int m0 = mt * 128;
        // ---- store staged A tile to smem buffer ----
        __half2* A = sA + buf * AS_ELEMS;
#pragma unroll
        for (int j = 0; j < 8; j++) {
            int i = tid + j * 512;
            int r = i >> 5, q = i & 31;
            uint2 p = make_uint2(stage[j * 2], stage[j * 2 + 1]);
            *reinterpret_cast<uint2*>(&A[r * AS_STRIDE + q * 2]) = p;
        }
        __syncthreads();

        // ---- prefetch next tile while computing ----
        const int mnext = mt + GEMM_GRID;
        if (mnext < NTILES) {
            int m0n = mnext * 128;
#pragma unroll
            for (int j = 0; j < 8; j++) {
                int i = tid + j * 512;
                int r = i >> 5, q = i & 31;
                int row = m0n + r;
                if (FIRST) {
                    float4 v = make_float4(0.f, 0.f, 0.f, 0.f);
                    if (row < N_NODES) v = A4[(size_t)row * NQUAD + q];
                    stage[j * 2    ] = h2u(__floats2half2_rn(v.x, v.y));
                    stage[j * 2 + 1] = h2u(__floats2half2_rn(v.z, v.w));
                } else {
                    uint2 p = make_uint2(0u, 0u);
                    if (row < N_NODES) p = B2[(size_t)row * 32 + q];
                    stage[j * 2    ] = p.x;
                    stage[j * 2 + 1] = p.y;
                }
            }
        }

        // per-tile ldmatrix base addresses (A buffer changed)
        uint32_t abase0 = (uint32_t)__cvta_generic_to_shared(
            &A[(wm * 32 +       lrow) * AS_STRIDE + lcol]);
        uint32_t abase1 = (uint32_t)__cvta_generic_to_shared(
            &A[(wm * 32 + 16 +  lrow) * AS_STRIDE + lcol]);

        // ---- compute: 8 k16 chunks ----
        float acc[2][4][4] = {};
#pragma unroll
        for (int c = 0; c < 8; c++) {
            const int h2 = c * 8;                // half2 (A) / kpair (B) base
            uint32_t af[2][4];
            ldsm_x4(af[0][0], af[0][1], af[0][2], af[0][3], abase0 + c * 32);
            ldsm_x4(af[1][0], af[1][1], af[1][2], af[1][3], abase1 + c * 32);
#pragma unroll
            for (int fn = 0; fn < 4; fn++) {
                int cn = wn * 32 + fn * 8 + gid;
                uint32_t b0 = h2u(sB[(h2 + tig    ) * BS_STRIDE + cn]);
                uint32_t b1 = h2u(sB[(h2 + tig + 4) * BS_STRIDE + cn]);
                mma_f16(acc[0][fn], af[0], b0, b1);
                mma_f16(acc[1][fn], af[1], b0, b1);
            }
        }

        // ---- epilogue ----
#pragma unroll
        for (int fm = 0; fm < 2; fm++) {
            int r0 = m0 + wm * 32 + fm * 16 + gid;
            int r1 = r0 + 8;
            float d0 = 1.f, d1 = 1.f;
            if (!FIRST) {
                d0 = (r0 < N_NODES) ? g_dinv[r0] : 0.f;
                d1 = (r1 < N_NODES) ? g_dinv[r1] : 0.f;
            }
#pragma unroll
            for (int fn = 0; fn < 4; fn++) {
                int h2i = wn * 16 + fn * 4 + tig;
                if (r0 < N_NODES)
                    g_h[(size_t)r0 * 64 + h2i] =
                        __floats2half2_rn(acc[fm][fn][0] * d0, acc[fm][fn][1] * d0);
                if (r1 < N_NODES)
                    g_h[(size_t)r1 * 64 + h2i] =
                        __floats2half2_rn(acc[fm][fn][2] * d1, acc[fm][fn][3] * d1);
            }
        }

        mt = mnext;
        buf ^= 1;
    }
}

// ---------------- aggregation: warp per node, pre-scaled rows ----------
// out[d] = relu( dv_d * ( g[d] + sum_s g[s] ) + b ),  g already carries dinv[s]
template <bool LAST>
__global__ __launch_bounds__(256) void k_agg(const float* __restrict__ bias,
                                             float* __restrict__ outExt) {
    int gw   = (blockIdx.x * blockDim.x + threadIdx.x) >> 5;
    int lane = threadIdx.x & 31;
    if (gw >= N_NODES) return;

    const uint2* H = reinterpret_cast<const uint2*>(g_h);   // 32 uint2 per row

    float4 acc;
    {
        uint2 u = H[(size_t)gw * 32 + lane];                // self-loop term
        float2 f0 = __half22float2(*reinterpret_cast<__half2*>(&u.x));
        float2 f1 = __half22float2(*reinterpret_cast<__half2*>(&u.y));
        acc = make_float4(f0.x, f0.y, f1.x, f1.y);
    }
    const int beg = g_rowptr[gw], end = g_rowptr[gw + 1];

    for (int j = beg; j < end; j += 32) {
        int jl  = j + lane;
        int idx = (jl < end) ? g_col[jl] : 0;
        int cnt = min(32, end - j);
        int t = 0;
        for (; t + 8 <= cnt; t += 8) {           // 8 independent gathers in flight
            uint2 v[8];
#pragma unroll
            for (int u = 0; u < 8; u++) {
                int s = __shfl_sync(0xffffffffu, idx, t + u);
                v[u] = H[(size_t)s * 32 + lane];
            }
#pragma unroll
            for (int u = 0; u < 8; u++) {
                float2 f0 = __half22float2(*reinterpret_cast<__half2*>(&v[u].x));
                float2 f1 = __half22float2(*reinterpret_cast<__half2*>(&v[u].y));
                acc.x += f0.x; acc.y += f0.y; acc.z += f1.x; acc.w += f1.y;
            }
        }
        for (; t < cnt; t++) {
            int s = __shfl_sync(0xffffffffu, idx, t);
            uint2 u = H[(size_t)s * 32 + lane];
            float2 f0 = __half22float2(*reinterpret_cast<__half2*>(&u.x));
            float2 f1 = __half22float2(*reinterpret_cast<__half2*>(&u.y));
            acc.x += f0.x; acc.y += f0.y; acc.z += f1.x; acc.w += f1.y;
        }
    }

    float dv  = g_dinv[gw];
    float4 bb = reinterpret_cast<const float4*>(bias)[lane];
    float4 o;
    o.x = fmaxf(fmaf(acc.x, dv, bb.x), 0.f);
    o.y = fmaxf(fmaf(acc.y, dv, bb.y), 0.f);
    o.z = fmaxf(fmaf(acc.z, dv, bb.z), 0.f);
    o.w = fmaxf(fmaf(acc.w, dv, bb.w), 0.f);
    if (LAST) {
        reinterpret_cast<float4*>(outExt)[(size_t)gw * NQUAD + lane] = o;
    } else {
        uint2 p;
        p.x = h2u(__floats2half2_rn(o.x, o.y));
        p.y = h2u(__floats2half2_rn(o.z, o.w));
        reinterpret_cast<uint2*>(g_bufh)[(size_t)gw * 32 + lane] = p;
    }
}

// ---------------- launch ----------------
extern "C" void kernel_launch(void* const* d_in, const int* in_sizes, int n_in,
                              void* d_out, int out_size) {
    const float* x  = (const float*)d_in[0];
    const int*   ei = (const int*)d_in[1];          // int32 edge_index
    const float* W0 = (const float*)d_in[2];
    const float* b0 = (const float*)d_in[3];
    const float* W1 = (const float*)d_in[4];
    const float* b1 = (const float*)d_in[5];
    const float* W2 = (const float*)d_in[6];
    const float* b2 = (const float*)d_in[7];
    float* out = (float*)d_out;

    const int nodeBlocks  = (N_NODES + 255) / 256;
    const int edgeBlocks  = (N_EDGES + 255) / 256;
    const int scanBlocks  = (N_NODES + 1023) / 1024;   // 98
    const int aggBlocks   = (N_NODES * 32 + 255) / 256;
    const int scaleBlocks = (N_NODES * 32 + 255) / 256;

    cudaFuncSetAttribute(k_gemm_f16<true>,
                         cudaFuncAttributeMaxDynamicSharedMemorySize, SMEM_GEMM);
    cudaFuncSetAttribute(k_gemm_f16<false>,
                         cudaFuncAttributeMaxDynamicSharedMemorySize, SMEM_GEMM);

    // Fork-join: CSR build on side stream s2; gemm0 (unscaled) overlaps on main.
    // k_scale gates only on scan3 (eS) -> overlaps k_scatter. agg0 gates on eJ.
    cudaStream_t s2;
    cudaStreamCreate(&s2);
    cudaEvent_t eF, eS, eJ;
    cudaEventCreateWithFlags(&eF, cudaEventDisableTiming);
    cudaEventCreateWithFlags(&eS, cudaEventDisableTiming);
    cudaEventCreateWithFlags(&eJ, cudaEventDisableTiming);

    cudaEventRecord(eF, 0);
    cudaStreamWaitEvent(s2, eF, 0);

    k_zero_deg<<<nodeBlocks, 256, 0, s2>>>();
    k_hist    <<<edgeBlocks, 256, 0, s2>>>(ei);
    k_scan1   <<<scanBlocks, 1024, 0, s2>>>();
    // gemm0 on main stream, concurrent with CSR build (disjoint data)
    k_gemm_f16<true><<<GEMM_GRID, 512, SMEM_GEMM>>>(x, W0);
    k_scan3   <<<nodeBlocks, 256, 0, s2>>>(scanBlocks);
    cudaEventRecord(eS, s2);
    k_scatter <<<edgeBlocks, 256, 0, s2>>>(ei);
    cudaEventRecord(eJ, s2);

    // k_scale needs gemm0 (main) + scan3 (eS); runs concurrent with scatter
    cudaStreamWaitEvent(0, eS, 0);
    k_scale   <<<scaleBlocks, 256>>>();

    // aggregation needs the full CSR
    cudaStreamWaitEvent(0, eJ, 0);
    k_agg     <false><<<aggBlocks, 256>>>(b0, nullptr);
    k_gemm_f16<false><<<GEMM_GRID, 512, SMEM_GEMM>>>(nullptr, W1);
    k_agg     <false><<<aggBlocks, 256>>>(b1, nullptr);
    k_gemm_f16<false><<<GEMM_GRID, 512, SMEM_GEMM>>>(nullptr, W2);
    k_agg     <true ><<<aggBlocks, 256>>>(b2, out);
}